// round 14
// baseline (speedup 1.0000x reference)
#include <cuda_runtime.h>
#include <cuda_bf16.h>

#define NS    125
#define NW    5
#define NZ    625
#define NR    500
#define DDIM  8192
#define NQ    2048
#define MAXIT 20
#define CGIT  12
#define NT    1024

__device__ float g_Kslice[8][16384];
__device__ float g_K[16384];
__device__ float g_z[NZ];
__device__ float g_P[NW * DDIM];

// 5x4 orthonormal basis of {v in R^5 : sum v = 0} (Householder complement of 1/sqrt5)
__constant__ float cZ[5][4] = {
    { 0.44721360f,  0.44721360f,  0.44721360f,  0.44721360f},
    { 0.63819660f, -0.36180340f, -0.36180340f, -0.36180340f},
    {-0.36180340f,  0.63819660f, -0.36180340f, -0.36180340f},
    {-0.36180340f, -0.36180340f,  0.63819660f, -0.36180340f},
    {-0.36180340f, -0.36180340f, -0.36180340f,  0.63819660f}};

// ---------------- K = S S^T, split-K over 8 slices (deterministic) ----------------
__global__ void k_gemmK(const float* __restrict__ sup) {
    __shared__ float As[16][17], Bs[16][17];
    const int tx = threadIdx.x, ty = threadIdx.y;
    const int bi = blockIdx.y * 16, bj = blockIdx.x * 16;
    const int row = bi + ty;
    float acc = 0.f;
    for (int k0 = blockIdx.z * 1024; k0 < blockIdx.z * 1024 + 1024; k0 += 16) {
        As[ty][tx] = (row < NS) ? sup[(long)row * DDIM + k0 + tx] : 0.f;
        Bs[ty][tx] = (bj + ty < NS) ? sup[(long)(bj + ty) * DDIM + k0 + tx] : 0.f;
        __syncthreads();
#pragma unroll
        for (int k = 0; k < 16; k++) acc += As[ty][k] * Bs[tx][k];
        __syncthreads();
    }
    g_Kslice[blockIdx.z][(bi + ty) * 128 + (bj + tx)] = acc;
}

__global__ void k_reduceK() {
    int idx = blockIdx.x * blockDim.x + threadIdx.x;
    float a = 0.f;
#pragma unroll
    for (int s = 0; s < 8; s++) a += g_Kslice[s][idx];
    g_K[idx] = a;
}

// ---------------- block reductions ----------------
__device__ __forceinline__ float blkSum(float v, float* sc) {
#pragma unroll
    for (int o = 16; o; o >>= 1) v += __shfl_down_sync(0xffffffffu, v, o);
    if ((threadIdx.x & 31) == 0) sc[threadIdx.x >> 5] = v;
    __syncthreads();
    if (threadIdx.x < 32) {
        float x = sc[threadIdx.x];
#pragma unroll
        for (int o = 16; o; o >>= 1) x += __shfl_down_sync(0xffffffffu, x, o);
        if (threadIdx.x == 0) sc[32] = x;
    }
    __syncthreads();
    float r = sc[32];
    __syncthreads();
    return r;
}

__device__ __forceinline__ float blkMin(float v, float* sc) {
#pragma unroll
    for (int o = 16; o; o >>= 1) v = fminf(v, __shfl_down_sync(0xffffffffu, v, o));
    if ((threadIdx.x & 31) == 0) sc[threadIdx.x >> 5] = v;
    __syncthreads();
    if (threadIdx.x < 32) {
        float x = sc[threadIdx.x];
#pragma unroll
        for (int o = 16; o; o >>= 1) x = fminf(x, __shfl_down_sync(0xffffffffu, x, o));
        if (threadIdx.x == 0) sc[32] = x;
    }
    __syncthreads();
    float r = sc[32];
    __syncthreads();
    return r;
}

// K matvec with K register-resident: thread t<1000 holds K[t%125][16*(t/125) .. +15]
template <int NC>
__device__ __forceinline__ void kmatvec(const float (&kr)[16], int i_, int seg, bool act,
                                        const float* V, float* Y, float* part) {
    if (act) {
        float ps[NC];
#pragma unroll
        for (int c = 0; c < NC; c++) ps[c] = 0.f;
        const int jb = seg * 16;
#pragma unroll
        for (int k = 0; k < 16; k++) {
            float f = kr[k];
#pragma unroll
            for (int c = 0; c < NC; c++) ps[c] += f * V[(jb + k) * NC + c];
        }
#pragma unroll
        for (int c = 0; c < NC; c++) part[(c * 8 + seg) * 128 + i_] = ps[c];
    }
    __syncthreads();
    for (int u = threadIdx.x; u < NS * NC; u += NT) {
        int c = u / NS, ii = u - c * NS;
        float acc = 0.f;
#pragma unroll
        for (int g = 0; g < 8; g++) acc += part[(c * 8 + g) * 128 + ii];
        Y[ii * NC + c] = acc;
    }
    __syncthreads();
}

// smem float offsets
#define O_Z     0
#define O_S     640
#define O_LAM   1265
#define O_DD    1890
#define O_R2    2515
#define O_R3    3140
#define O_RHS   3765
#define O_CB    4390
#define O_DZ    5015
#define O_TV    5640
#define O_KT    5768
#define O_KD    5896
#define O_NU    6024
#define O_XS    6152
#define O_RS    6664
#define O_ZV    7176
#define O_AP    7688
#define O_PS    8200
#define O_MINV  8712
#define O_BSM   10712
#define O_PART  12712
#define O_SC    17832
#define O_LB    17896
#define SMEM_FLOATS 18024
#define SMEM_BYTES  (SMEM_FLOATS * 4)

__global__ void __launch_bounds__(NT, 1)
k_ipm(const int* __restrict__ lblg, float* __restrict__ out, int out_size) {
    extern __shared__ float sm[];
    float* Z = sm + O_Z;     float* S = sm + O_S;     float* LAM = sm + O_LAM;
    float* DDv = sm + O_DD;  float* R2 = sm + O_R2;   float* R3 = sm + O_R3;
    float* RHS = sm + O_RHS; float* CB = sm + O_CB;   float* DZ = sm + O_DZ;
    float* TV = sm + O_TV;   float* KT = sm + O_KT;   float* KD = sm + O_KD;
    float* NU = sm + O_NU;   float* XS = sm + O_XS;   float* RS = sm + O_RS;
    float* ZV = sm + O_ZV;   float* AP = sm + O_AP;   float* PS = sm + O_PS;
    float* MINV = sm + O_MINV; float* BSM = sm + O_BSM; float* PART = sm + O_PART;
    float* SC = sm + O_SC;   int* LB = (int*)(sm + O_LB);

    const int t = threadIdx.x;
    const int i_ = t % NS, seg = t / NS;
    const bool act = (t < 1000);

    float kr[16];
#pragma unroll
    for (int k = 0; k < 16; k++) kr[k] = act ? g_K[i_ * 128 + seg * 16 + k] : 0.f;

    for (int u = t; u < 640; u += NT) Z[u] = 0.f;
    if (t < NZ)  { S[t] = 1.f; LAM[t] = 1.f; }
    if (t < 128) { NU[t] = 0.f; TV[t] = 0.f; }
    if (t < 512) { PS[t] = 0.f; }
    if (t < NS)  { KD[t] = g_K[t * 128 + t]; LB[t] = lblg[t]; }
    __syncthreads();

    for (int it = 0; it < MAXIT; it++) {
        // KZ (5 cols) -> DZ buffer
        kmatvec<5>(kr, i_, seg, act, Z, DZ, PART);
        float mu = 0.1f * blkSum((t < NZ) ? S[t] * LAM[t] : 0.f, SC) * (1.f / 625.f);

        if (t < NZ) {
            int ii = t / NW, w = t - ii * NW;
            float e = (LB[ii] == w) ? -1.f : 0.f;
            float h = (LB[ii] == w) ? 0.1f : 0.f;
            float sv = S[t], lv = LAM[t], zv = Z[t];
            float r1 = (DZ[t] + zv) + e + lv + NU[ii];
            float r2v = zv + sv - h;
            float r3v = lv * sv - mu;
            R2[t] = r2v; R3[t] = r3v; DDv[t] = lv / sv;
            RHS[t] = -(r1 + (lv * r2v - r3v) / sv);
        }
        if (t < NS) {
            float r4 = Z[t*5] + Z[t*5+1] + Z[t*5+2] + Z[t*5+3] + Z[t*5+4];
            TV[t] = -0.2f * r4;                       // particular dz (same per way)
        }
        __syncthreads();

        kmatvec<1>(kr, i_, seg, act, TV, KT, PART);   // K * TV

        if (t < NZ) {
            int ii = t / NW;
            CB[t] = RHS[t] - KT[ii] - TV[ii] * (1.f + DDv[t]);  // c = rhs1 - H dz_p
        }
        if (t < NS) {
            float dd[5];
#pragma unroll
            for (int w = 0; w < NW; w++) dd[w] = DDv[t * NW + w];
            float M[4][4], Inv[4][4];
#pragma unroll
            for (int a = 0; a < 4; a++)
#pragma unroll
                for (int b = 0; b < 4; b++) {
                    float s2 = 0.f;
#pragma unroll
                    for (int w = 0; w < NW; w++) s2 += cZ[w][a] * dd[w] * cZ[w][b];
                    BSM[t * 16 + a * 4 + b] = s2;
                    M[a][b] = s2;
                    Inv[a][b] = (a == b) ? 1.f : 0.f;
                }
            float dg = KD[t] + 1.f;
#pragma unroll
            for (int a = 0; a < 4; a++) M[a][a] += dg;
#pragma unroll
            for (int k = 0; k < 4; k++) {
                float piv = 1.f / M[k][k];
#pragma unroll
                for (int c = 0; c < 4; c++) { M[k][c] *= piv; Inv[k][c] *= piv; }
#pragma unroll
                for (int r = 0; r < 4; r++) if (r != k) {
                    float f = M[r][k];
#pragma unroll
                    for (int c = 0; c < 4; c++) { M[r][c] -= f * M[k][c]; Inv[r][c] -= f * Inv[k][c]; }
                }
            }
#pragma unroll
            for (int a = 0; a < 4; a++)
#pragma unroll
                for (int b = 0; b < 4; b++) MINV[t * 16 + a * 4 + b] = Inv[a][b];
        }
        __syncthreads();

        // reduced rhs bq = Z^T c ; PCG init
        if (t < NR) {
            int ii = t / 4, a = t - ii * 4;
            float bv = 0.f;
#pragma unroll
            for (int w = 0; w < NW; w++) bv += cZ[w][a] * CB[ii * NW + w];
            RS[t] = bv; XS[t] = 0.f;
        }
        __syncthreads();
        if (t < NR) {
            int ii = t / 4, a = t - ii * 4;
            float zz = 0.f;
#pragma unroll
            for (int b = 0; b < 4; b++) zz += MINV[ii * 16 + a * 4 + b] * RS[ii * 4 + b];
            ZV[t] = zz; PS[t] = zz;
        }
        float rho = blkSum((t < NR) ? RS[t] * ZV[t] : 0.f, SC);

        for (int cg = 0; cg < CGIT; cg++) {
            __syncthreads();
            kmatvec<4>(kr, i_, seg, act, PS, AP, PART);
            if (t < NR) {
                int ii = t / 4, a = t - ii * 4;
                float v = AP[t] + PS[t];
#pragma unroll
                for (int b = 0; b < 4; b++) v += BSM[ii * 16 + a * 4 + b] * PS[ii * 4 + b];
                AP[t] = v;
            }
            float pAp = blkSum((t < NR) ? PS[t] * AP[t] : 0.f, SC);
            float al = (pAp > 1e-37f) ? rho / pAp : 0.f;
            if (t < NR) { XS[t] += al * PS[t]; RS[t] -= al * AP[t]; }
            __syncthreads();
            if (t < NR) {
                int ii = t / 4, a = t - ii * 4;
                float zz = 0.f;
#pragma unroll
                for (int b = 0; b < 4; b++) zz += MINV[ii * 16 + a * 4 + b] * RS[ii * 4 + b];
                ZV[t] = zz;
            }
            float rho2 = blkSum((t < NR) ? RS[t] * ZV[t] : 0.f, SC);
            float be = (rho > 1e-37f) ? rho2 / rho : 0.f;
            rho = rho2;
            if (t < NR) PS[t] = ZV[t] + be * PS[t];
        }
        __syncthreads();

        // dz, ds, dlam, dnu, step
        float ds = 0.f, dlam = 0.f, rloc = 3.4e38f;
        if (t < NZ) {
            int ii = t / NW, w = t - ii * NW;
            float zx = 0.f;
#pragma unroll
            for (int a = 0; a < 4; a++) zx += cZ[w][a] * XS[ii * 4 + a];
            float dz = TV[ii] + zx;
            DZ[t] = dz;
            CB[t] = RHS[t] - DDv[t] * dz;          // for dnu
            ds = -R2[t] - dz;
            dlam = (-R3[t] - LAM[t] * ds) / S[t];
            float ra = (ds < 0.f) ? -S[t] / ds : 3.4e38f;
            float rb = (dlam < 0.f) ? -LAM[t] / dlam : 3.4e38f;
            rloc = fminf(ra, rb);
        }
        float alpha = fminf(1.f, 0.99f * blkMin(rloc, SC));
        if (t < NS) {
            float dnu = 0.2f * (CB[t*5] + CB[t*5+1] + CB[t*5+2] + CB[t*5+3] + CB[t*5+4])
                        - KT[t] - TV[t];
            NU[t] += alpha * dnu;
        }
        if (t < NZ) {
            Z[t]   += alpha * DZ[t];
            S[t]   += alpha * ds;
            LAM[t] += alpha * dlam;
        }
        __syncthreads();
    }

    if (t < NZ) g_z[t] = Z[t];
    float sv = 0.f;
    if (t < NS) {
        bool any = false;
#pragma unroll
        for (int w = 0; w < NW; w++) any = any || (Z[t * NW + w] > 0.001f);
        sv = any ? 1.f : 0.f;
    }
    float nsv = blkSum(sv, SC);
    for (int u = NQ * NW + t; u < out_size; u += NT) out[u] = nsv;
}

// ---------------- P[w][d] = sum_i z[i,w] * sup[i][d] ----------------
__global__ void k_proj(const float* __restrict__ sup) {
    __shared__ float zs[NZ];
    for (int u = threadIdx.x; u < NZ; u += blockDim.x) zs[u] = g_z[u];
    __syncthreads();
    int d = blockIdx.x * blockDim.x + threadIdx.x;
    float acc[NW];
#pragma unroll
    for (int w = 0; w < NW; w++) acc[w] = 0.f;
    for (int i = 0; i < NS; i++) {
        float f = sup[(long)i * DDIM + d];
#pragma unroll
        for (int w = 0; w < NW; w++) acc[w] += zs[i * NW + w] * f;
    }
#pragma unroll
    for (int w = 0; w < NW; w++) g_P[w * DDIM + d] = acc[w];
}

// ---------------- logits[q][w] = scale * dot(Q[q], P[w]) ----------------
__global__ void k_logits(const float* __restrict__ query, const float* __restrict__ scale,
                         float* __restrict__ out) {
    int warp = (blockIdx.x * blockDim.x + threadIdx.x) >> 5;
    int lane = threadIdx.x & 31;
    if (warp >= NQ) return;
    const float4* q4 = (const float4*)(query + (long)warp * DDIM);
    const float4* p4 = (const float4*)g_P;
    float acc[NW];
#pragma unroll
    for (int w = 0; w < NW; w++) acc[w] = 0.f;
    for (int j = lane; j < DDIM / 4; j += 32) {
        float4 q = q4[j];
#pragma unroll
        for (int w = 0; w < NW; w++) {
            float4 p = p4[w * (DDIM / 4) + j];
            acc[w] += q.x * p.x + q.y * p.y + q.z * p.z + q.w * p.w;
        }
    }
#pragma unroll
    for (int w = 0; w < NW; w++) {
#pragma unroll
        for (int o = 16; o; o >>= 1) acc[w] += __shfl_down_sync(0xffffffffu, acc[w], o);
    }
    if (lane == 0) {
        float sc = scale[0];
#pragma unroll
        for (int w = 0; w < NW; w++) out[warp * NW + w] = sc * acc[w];
    }
}

extern "C" void kernel_launch(void* const* d_in, const int* in_sizes, int n_in,
                              void* d_out, int out_size) {
    const float* query = nullptr;
    const float* support = nullptr;
    const int* labels = nullptr;
    for (int i = 0; i < n_in; i++) {
        if (in_sizes[i] == NQ * DDIM) query = (const float*)d_in[i];
        else if (in_sizes[i] == NS * DDIM) support = (const float*)d_in[i];
        else if (in_sizes[i] == NS) labels = (const int*)d_in[i];
    }
    const float* scale = (const float*)d_in[n_in - 1];
    float* out = (float*)d_out;

    static int smem_set = 0;
    if (!smem_set) {
        cudaFuncSetAttribute(k_ipm, cudaFuncAttributeMaxDynamicSharedMemorySize, SMEM_BYTES);
        smem_set = 1;
    }

    k_gemmK<<<dim3(8, 8, 8), dim3(16, 16)>>>(support);
    k_reduceK<<<16, 1024>>>();
    k_ipm<<<1, NT, SMEM_BYTES>>>(labels, out, out_size);
    k_proj<<<DDIM / 1024, 1024>>>(support);
    k_logits<<<(NQ * 32 + 255) / 256, 256>>>(query, scale, out);
}